// round 11
// baseline (speedup 1.0000x reference)
#include <cuda_runtime.h>
#include <cuda_bf16.h>
#include <cuda_fp16.h>
#include <mma.h>
#include <math.h>

using namespace nvcuda;

#define NN    100000
#define EE    1600000
#define H     128
#define HEADS 4
#define DOUT  32
#define G     64
#define FOUT  256
#define NEG_SLOPE 0.2f
#define PAD   64        // padded CSR stride == smem cache capacity (max in-degree ~40)
#define GT    782       // ceil(NN/128) GEMM tiles
#define GEMM_GRID 152   // persistent CTAs (1 per SM on GB300)

// GEMM smem geometry: [sW 128x136 bf16][sA 2x128x136 bf16][sC 128x132 f32]
#define SAB_STRIDE 136
#define SW_BYTES   (128 * SAB_STRIDE * 2)          // 34816
#define SA_BYTES   (128 * SAB_STRIDE * 2)          // per buffer
#define SC_STRIDE  132
#define SC_BYTES   (128 * SC_STRIDE * 4)           // 67584
#define GEMM_SMEM  (SW_BYTES + 2 * SA_BYTES + SC_BYTES)   // 172032

// ---------------- scratch (device globals; no allocation allowed) ----------------
__device__ float         d_h[NN * H];       // current node features (fp32)
__device__ __nv_bfloat16 d_hb[NN * H];      // bf16 mirror of d_h (GEMM A input)
__device__ __half        d_hph[NN * H];     // h @ W in fp16 (gather source)
__device__ __nv_bfloat16 d_Wb[2][H * H];    // bf16 weights (pre-converted)
__device__ float         d_als[NN * HEADS];
__device__ float         d_ald[NN * HEADS];
__device__ int           d_deg[NN];
__device__ int           d_csr_src[(size_t)NN * PAD];
__device__ float         d_msum[G * H];
__device__ unsigned      d_mxenc[G * H];
__device__ float         d_cnt[G];

// ---------------- helpers ----------------
__device__ __forceinline__ unsigned fenc(float f) {
    unsigned u = __float_as_uint(f);
    return (u & 0x80000000u) ? ~u : (u | 0x80000000u);
}
__device__ __forceinline__ float fdec(unsigned e) {
    return (e & 0x80000000u) ? __uint_as_float(e & 0x7fffffffu)
                             : __uint_as_float(~e);
}
__device__ __forceinline__ float gelu_exact(float v) {
    return 0.5f * v * (1.0f + erff(v * 0.70710678118654752f));
}
__device__ __forceinline__ float lrelu(float v) {
    return v > 0.f ? v : NEG_SLOPE * v;
}
__device__ __forceinline__ void cp16(void* s, const void* g, bool valid) {
    unsigned sa = (unsigned)__cvta_generic_to_shared(s);
    int sz = valid ? 16 : 0;
    asm volatile("cp.async.cg.shared.global [%0], [%1], 16, %2;\n"
                 :: "r"(sa), "l"(g), "r"(sz));
}

// ---------------- trailing zero (restores invariant for next call) ----------------
__global__ void k_zero() {
    int t = blockIdx.x * blockDim.x + threadIdx.x;
    if (t < NN) d_deg[t] = 0;
    if (t < G * H) { d_msum[t] = 0.f; d_mxenc[t] = 0u; }
    if (t < G) d_cnt[t] = 0.f;
}

// ---------------- merged setup: CSR fill | input proj | W conversion ----------------
__global__ void k_prep(const int* __restrict__ ei, const float* __restrict__ x,
                       const float* __restrict__ Wp, const float* __restrict__ bp,
                       const float* __restrict__ Wg0, const float* __restrict__ Wg1) {
    __shared__ float sW[16 * 128];
    __shared__ float sx[32][16];
    int b = blockIdx.x;
    int tid = threadIdx.x;          // 256
    if (b < 3125) {
        int e0 = (b * 256 + tid) * 2;
        if (e0 >= EE) return;
        int2 s2 = *(const int2*)(ei + e0);
        int2 dd = *(const int2*)(ei + EE + e0);
        {
            int p = atomicAdd(&d_deg[dd.x], 1);
            if (p < PAD) d_csr_src[(size_t)dd.x * PAD + p] = s2.x;
        }
        {
            int p = atomicAdd(&d_deg[dd.y], 1);
            if (p < PAD) d_csr_src[(size_t)dd.y * PAD + p] = s2.y;
        }
    } else if (b < 6250) {
        int base = (b - 3125) * 32;
        for (int i = tid; i < 16 * 128; i += 256) sW[i] = Wp[i];
        for (int i = tid; i < 32 * 16; i += 256) {
            int r = i >> 4, c = i & 15;
            sx[r][c] = (base + r < NN) ? x[(base + r) * 16 + c] : 0.f;
        }
        __syncthreads();
        int col  = tid & 127;
        int half = tid >> 7;
        float w[16];
#pragma unroll
        for (int k = 0; k < 16; k++) w[k] = sW[k * 128 + col];
        float bb = bp[col];
        for (int n = half * 16; n < half * 16 + 16; n++) {
            int row = base + n;
            if (row >= NN) break;
            float acc = bb;
#pragma unroll
            for (int k = 0; k < 16; k++) acc = fmaf(sx[n][k], w[k], acc);
            float v = gelu_exact(acc);
            d_h[row * H + col]  = v;
            d_hb[row * H + col] = __float2bfloat16(v);
        }
    } else {
        int bb = b - 6250;              // 0..127
        int layer = bb >> 6;
        int off = (bb & 63) * 256 + tid;
        const float* Wsrc = layer ? Wg1 : Wg0;
        d_Wb[layer][off] = __float2bfloat16(Wsrc[off]);
    }
}

// ---------------- persistent pipelined tensor-core GEMM + fused epilogue -------
// grid=GEMM_GRID, 256 threads = 8 warps. W in smem once; A double-buffered with
// cp.async prefetch of the next tile overlapping MMA+epilogue of the current.
__global__ __launch_bounds__(256, 1) void k_gemm(int layer,
                                                 const float* __restrict__ a_s,
                                                 const float* __restrict__ a_d) {
    extern __shared__ char smem[];
    __nv_bfloat16* sW = (__nv_bfloat16*)smem;                        // [128][136]
    __nv_bfloat16* sA0 = (__nv_bfloat16*)(smem + SW_BYTES);          // buf 0
    __nv_bfloat16* sA1 = (__nv_bfloat16*)(smem + SW_BYTES + SA_BYTES);
    float*         sC = (float*)(smem + SW_BYTES + 2 * SA_BYTES);    // [128][132]
    __nv_bfloat16* sAbuf[2] = {sA0, sA1};
    int tid  = threadIdx.x;
    int warp = tid >> 5;
    const __nv_bfloat16* Wb = d_Wb[layer];

    int r16 = tid >> 4;          // 0..15 (row group of 8 rows? no: see below)
    // load plan: 2048 16B-chunks per 128x128 tile -> 8 per thread
    // chunk idx = j*256+tid; row = idx>>4 (0..127), col-chunk = idx&15

    // initial group: W + A(tile0)
    int t0 = blockIdx.x;
#pragma unroll
    for (int j = 0; j < 8; j++) {
        int idx = j * 256 + tid;
        int r = idx >> 4, c = idx & 15;
        cp16(&sW[r * SAB_STRIDE + c * 8], &Wb[r * H + c * 8], true);
        int grow = t0 * 128 + r;
        cp16(&sA0[r * SAB_STRIDE + c * 8], &d_hb[(size_t)grow * H + c * 8], grow < NN);
    }
    asm volatile("cp.async.commit_group;");

    int rw = warp >> 1;         // row tile 0..3 (32 rows each)
    int ch = warp & 1;          // col half 0..1 (64 cols each)
    int buf = 0;

    for (int t = t0; t < GT; t += GEMM_GRID) {
        // prefetch next tile into the other buffer
        int tn = t + GEMM_GRID;
#pragma unroll
        for (int j = 0; j < 8; j++) {
            int idx = j * 256 + tid;
            int r = idx >> 4, c = idx & 15;
            int grow = tn * 128 + r;
            cp16(&sAbuf[buf ^ 1][r * SAB_STRIDE + c * 8],
                 &d_hb[(size_t)grow * H + c * 8], (tn < GT) && (grow < NN));
        }
        asm volatile("cp.async.commit_group;");
        asm volatile("cp.async.wait_group 1;");   // current tile resident
        __syncthreads();                          // also: prev epilogue done w/ sC

        const __nv_bfloat16* sA = sAbuf[buf];
        wmma::fragment<wmma::accumulator, 16, 16, 16, float> cf[2][4];
#pragma unroll
        for (int i = 0; i < 2; i++)
#pragma unroll
            for (int n = 0; n < 4; n++) wmma::fill_fragment(cf[i][n], 0.f);

#pragma unroll
        for (int k = 0; k < 8; k++) {
            wmma::fragment<wmma::matrix_a, 16, 16, 16, __nv_bfloat16, wmma::row_major> af[2];
            wmma::load_matrix_sync(af[0], sA + (rw * 32)      * SAB_STRIDE + k * 16, SAB_STRIDE);
            wmma::load_matrix_sync(af[1], sA + (rw * 32 + 16) * SAB_STRIDE + k * 16, SAB_STRIDE);
#pragma unroll
            for (int n = 0; n < 4; n++) {
                wmma::fragment<wmma::matrix_b, 16, 16, 16, __nv_bfloat16, wmma::row_major> bf;
                wmma::load_matrix_sync(bf, sW + (k * 16) * SAB_STRIDE + ch * 64 + n * 16, SAB_STRIDE);
                wmma::mma_sync(cf[0][n], af[0], bf, cf[0][n]);
                wmma::mma_sync(cf[1][n], af[1], bf, cf[1][n]);
            }
        }
#pragma unroll
        for (int i = 0; i < 2; i++)
#pragma unroll
            for (int n = 0; n < 4; n++)
                wmma::store_matrix_sync(sC + (rw * 32 + i * 16) * SC_STRIDE + ch * 64 + n * 16,
                                        cf[i][n], SC_STRIDE, wmma::mem_row_major);
        __syncthreads();

        // epilogue: 2 threads per row, each owns 64 cols (= 2 heads)
        int row  = tid >> 1;
        int half = tid & 1;
        int grow = t * 128 + row;
        if (grow < NN) {
            int hd0 = half * 2;
            float ps0 = 0.f, ps1 = 0.f, pd0 = 0.f, pd1 = 0.f;
            const float* crow = sC + row * SC_STRIDE + half * 64;
#pragma unroll
            for (int c4 = 0; c4 < 16; c4++) {
                float4 v = *(const float4*)&crow[c4 * 4];
                __half2 h01 = __floats2half2_rn(v.x, v.y);
                __half2 h23 = __floats2half2_rn(v.z, v.w);
                uint2 uu = make_uint2(*(unsigned*)&h01, *(unsigned*)&h23);
                *(uint2*)(d_hph + (size_t)grow * H + half * 64 + c4 * 4) = uu;
                int col = half * 64 + c4 * 4;
                int hd  = col >> 5;
                int dci = col & 31;
                float4 av = __ldg((const float4*)&a_s[hd * DOUT + dci]);
                float4 dv = __ldg((const float4*)&a_d[hd * DOUT + dci]);
                float ips = v.x * av.x + v.y * av.y + v.z * av.z + v.w * av.w;
                float ipd = v.x * dv.x + v.y * dv.y + v.z * dv.z + v.w * dv.w;
                if (hd == hd0) { ps0 += ips; pd0 += ipd; }
                else           { ps1 += ips; pd1 += ipd; }
            }
            d_als[grow * 4 + hd0]     = ps0;
            d_als[grow * 4 + hd0 + 1] = ps1;
            d_ald[grow * 4 + hd0]     = pd0;
            d_ald[grow * 4 + hd0 + 1] = pd1;
        }
        buf ^= 1;
    }
}

// ---------------- fused GAT layer: softmax + aggregate + residual + bias + LN ---
__global__ __launch_bounds__(256) void k_gat(const float* __restrict__ bg,
                                             const float* __restrict__ g,
                                             const float* __restrict__ be,
                                             int writeBf) {
    __shared__ int   s_src[8][PAD];
    __shared__ float s_e[8][PAD * 4];
    int w = threadIdx.x >> 5, lane = threadIdx.x & 31;
    int n = blockIdx.x * 8 + w;
    if (n >= NN) return;
    size_t off0 = (size_t)n * PAD;
    int deg = d_deg[n];
    deg = deg < PAD ? deg : PAD;
    float4 aldn = ((const float4*)d_ald)[n];
    float4 asel = ((const float4*)d_als)[n];
    float4 es;
    es.x = __expf(lrelu(asel.x + aldn.x));
    es.y = __expf(lrelu(asel.y + aldn.y));
    es.z = __expf(lrelu(asel.z + aldn.z));
    es.w = __expf(lrelu(asel.w + aldn.w));

    // fused gather + exp + denom (deg<=64 -> <=2 iters)
    float4 sum = make_float4(0.f, 0.f, 0.f, 0.f);
    for (int i = lane; i < deg; i += 32) {
        int s = __ldg(&d_csr_src[off0 + i]);
        float4 a = __ldg(((const float4*)d_als) + s);
        float ex = __expf(lrelu(a.x + aldn.x));
        float ey = __expf(lrelu(a.y + aldn.y));
        float ez = __expf(lrelu(a.z + aldn.z));
        float ew = __expf(lrelu(a.w + aldn.w));
        s_src[w][i] = s;
        s_e[w][i * 4 + 0] = ex; s_e[w][i * 4 + 1] = ey;
        s_e[w][i * 4 + 2] = ez; s_e[w][i * 4 + 3] = ew;
        sum.x += ex; sum.y += ey; sum.z += ez; sum.w += ew;
    }
#pragma unroll
    for (int o = 16; o; o >>= 1) {
        sum.x += __shfl_xor_sync(0xffffffffu, sum.x, o);
        sum.y += __shfl_xor_sync(0xffffffffu, sum.y, o);
        sum.z += __shfl_xor_sync(0xffffffffu, sum.z, o);
        sum.w += __shfl_xor_sync(0xffffffffu, sum.w, o);
    }
    float4 rden;
    rden.x = 1.f / (sum.x + es.x + 1e-16f);
    rden.y = 1.f / (sum.y + es.y + 1e-16f);
    rden.z = 1.f / (sum.z + es.z + 1e-16f);
    rden.w = 1.f / (sum.w + es.w + 1e-16f);
    __syncwarp();

    // feature-parallel aggregation (fp16 gather), 8-way batched
    int head = lane >> 3;
    float rd  = head == 0 ? rden.x : head == 1 ? rden.y : head == 2 ? rden.z : rden.w;
    float esh = head == 0 ? es.x   : head == 1 ? es.y   : head == 2 ? es.z   : es.w;
    float4 acc = ((const float4*)(d_h + (size_t)n * H))[lane];
    float4 b4  = __ldg(((const float4*)bg) + lane);
    acc.x += b4.x; acc.y += b4.y; acc.z += b4.z; acc.w += b4.w;
    {
        float a0 = esh * rd;
        uint2 u = __ldg(((const uint2*)(d_hph + (size_t)n * H)) + lane);
        float2 f01 = __half22float2(*(__half2*)&u.x);
        float2 f23 = __half22float2(*(__half2*)&u.y);
        acc.x = fmaf(f01.x, a0, acc.x);
        acc.y = fmaf(f01.y, a0, acc.y);
        acc.z = fmaf(f23.x, a0, acc.z);
        acc.w = fmaf(f23.y, a0, acc.w);
    }
    int i = 0;
    for (; i + 8 <= deg; i += 8) {
        int   sv[8]; float av[8]; uint2 uv[8];
#pragma unroll
        for (int j = 0; j < 8; j++) {
            sv[j] = s_src[w][i + j];
            av[j] = s_e[w][(i + j) * 4 + head] * rd;
        }
#pragma unroll
        for (int j = 0; j < 8; j++)
            uv[j] = __ldg(((const uint2*)(d_hph + (size_t)sv[j] * H)) + lane);
#pragma unroll
        for (int j = 0; j < 8; j++) {
            float2 p = __half22float2(*(__half2*)&uv[j].x);
            float2 q = __half22float2(*(__half2*)&uv[j].y);
            acc.x = fmaf(p.x, av[j], acc.x); acc.y = fmaf(p.y, av[j], acc.y);
            acc.z = fmaf(q.x, av[j], acc.z); acc.w = fmaf(q.y, av[j], acc.w);
        }
    }
    for (; i + 4 <= deg; i += 4) {
        int   sv[4]; float av[4]; uint2 uv[4];
#pragma unroll
        for (int j = 0; j < 4; j++) {
            sv[j] = s_src[w][i + j];
            av[j] = s_e[w][(i + j) * 4 + head] * rd;
        }
#pragma unroll
        for (int j = 0; j < 4; j++)
            uv[j] = __ldg(((const uint2*)(d_hph + (size_t)sv[j] * H)) + lane);
#pragma unroll
        for (int j = 0; j < 4; j++) {
            float2 p = __half22float2(*(__half2*)&uv[j].x);
            float2 q = __half22float2(*(__half2*)&uv[j].y);
            acc.x = fmaf(p.x, av[j], acc.x); acc.y = fmaf(p.y, av[j], acc.y);
            acc.z = fmaf(q.x, av[j], acc.z); acc.w = fmaf(q.y, av[j], acc.w);
        }
    }
    for (; i < deg; i++) {
        int s = s_src[w][i];
        float a0 = s_e[w][i * 4 + head] * rd;
        uint2 u = __ldg(((const uint2*)(d_hph + (size_t)s * H)) + lane);
        float2 f01 = __half22float2(*(__half2*)&u.x);
        float2 f23 = __half22float2(*(__half2*)&u.y);
        acc.x = fmaf(f01.x, a0, acc.x);
        acc.y = fmaf(f01.y, a0, acc.y);
        acc.z = fmaf(f23.x, a0, acc.z);
        acc.w = fmaf(f23.y, a0, acc.w);
    }

    // fused layernorm -> d_h (+ bf16 mirror for next GEMM)
    float sm = acc.x + acc.y + acc.z + acc.w;
#pragma unroll
    for (int o = 16; o; o >>= 1) sm += __shfl_xor_sync(0xffffffffu, sm, o);
    float mu = sm * (1.f / 128.f);
    float dx = acc.x - mu, dy = acc.y - mu, dz = acc.z - mu, dw = acc.w - mu;
    float q = dx * dx + dy * dy + dz * dz + dw * dw;
#pragma unroll
    for (int o = 16; o; o >>= 1) q += __shfl_xor_sync(0xffffffffu, q, o);
    float rstd = rsqrtf(q * (1.f / 128.f) + 1e-5f);
    float4 gg = __ldg(((const float4*)g) + lane);
    float4 bb = __ldg(((const float4*)be) + lane);
    float4 o4;
    o4.x = dx * rstd * gg.x + bb.x;
    o4.y = dy * rstd * gg.y + bb.y;
    o4.z = dz * rstd * gg.z + bb.z;
    o4.w = dw * rstd * gg.w + bb.w;
    ((float4*)(d_h + (size_t)n * H))[lane] = o4;
    if (writeBf) {
        __nv_bfloat162 b01 = __floats2bfloat162_rn(o4.x, o4.y);
        __nv_bfloat162 b23 = __floats2bfloat162_rn(o4.z, o4.w);
        uint2 ub = make_uint2(*(unsigned*)&b01, *(unsigned*)&b23);
        *(uint2*)(d_hb + (size_t)n * H + lane * 4) = ub;
    }
}

// ---------------- pooling ----------------
__global__ void k_pool(const int* __restrict__ n2g) {
    __shared__ int sg[32];
    int base = blockIdx.x * 32;
    int c = threadIdx.x; // 128
    if (c < 32) sg[c] = (base + c < NN) ? n2g[base + c] : -1;
    __syncthreads();
    float sum = 0.f, mx = -3.4e38f;
    int gcur = sg[0];
    int cl = 0;
    for (int i = 0; i < 32; i++) {
        int node = base + i;
        if (node >= NN) break;
        int gg = sg[i];
        if (gg != gcur) {
            atomicAdd(&d_msum[gcur * H + c], sum);
            atomicMax(&d_mxenc[gcur * H + c], fenc(mx));
            if (c == 0) atomicAdd(&d_cnt[gcur], (float)cl);
            sum = 0.f; mx = -3.4e38f; cl = 0; gcur = gg;
        }
        float v = d_h[(size_t)node * H + c];
        sum += v; mx = fmaxf(mx, v); cl++;
    }
    atomicAdd(&d_msum[gcur * H + c], sum);
    atomicMax(&d_mxenc[gcur * H + c], fenc(mx));
    if (c == 0) atomicAdd(&d_cnt[gcur], (float)cl);
}

// ---------------- head MLP ----------------
__global__ void k_head(const float* __restrict__ Wq1, const float* __restrict__ bq1,
                       const float* __restrict__ gq, const float* __restrict__ beq,
                       const float* __restrict__ Wq2, const float* __restrict__ bq2,
                       float* __restrict__ out) {
    __shared__ float semb[256];
    __shared__ float sp[128];
    __shared__ float sred[8];
    int g = blockIdx.x;
    int t = threadIdx.x; // 128
    float c = fmaxf(d_cnt[g], 1.f);
    semb[t]       = d_msum[g * H + t] / c;
    semb[128 + t] = fdec(d_mxenc[g * H + t]);
    __syncthreads();
    float p = bq1[t];
    for (int k = 0; k < 256; k++) p = fmaf(semb[k], Wq1[k * 128 + t], p);
    float s = p;
#pragma unroll
    for (int o = 16; o; o >>= 1) s += __shfl_xor_sync(0xffffffffu, s, o);
    if ((t & 31) == 0) sred[t >> 5] = s;
    __syncthreads();
    float mu = (sred[0] + sred[1] + sred[2] + sred[3]) * (1.f / 128.f);
    float dx = p - mu;
    float q = dx * dx;
#pragma unroll
    for (int o = 16; o; o >>= 1) q += __shfl_xor_sync(0xffffffffu, q, o);
    if ((t & 31) == 0) sred[4 + (t >> 5)] = q;
    __syncthreads();
    float var = (sred[4] + sred[5] + sred[6] + sred[7]) * (1.f / 128.f);
    float v = dx * rsqrtf(var + 1e-5f) * gq[t] + beq[t];
    sp[t] = gelu_exact(v);
    __syncthreads();
#pragma unroll
    for (int half = 0; half < 2; half++) {
        int o = t + half * 128;
        float acc = bq2[o];
        for (int k = 0; k < 128; k++) acc = fmaf(sp[k], Wq2[k * 256 + o], acc);
        out[g * 256 + o] = acc;
    }
}

// ---------------- launch ----------------
extern "C" void kernel_launch(void* const* d_in, const int* in_sizes, int n_in,
                              void* d_out, int out_size) {
    const float* x   = (const float*)d_in[0];
    const int*   ei  = (const int*)  d_in[1];
    const int*   n2g = (const int*)  d_in[2];
    const float* Wp  = (const float*)d_in[3];
    const float* bp  = (const float*)d_in[4];
    const float* Wq1 = (const float*)d_in[5];
    const float* bq1 = (const float*)d_in[6];
    const float* gq  = (const float*)d_in[7];
    const float* beq = (const float*)d_in[8];
    const float* Wq2 = (const float*)d_in[9];
    const float* bq2 = (const float*)d_in[10];
    const float* Wg[2]  = {(const float*)d_in[11], (const float*)d_in[17]};
    const float* as_[2] = {(const float*)d_in[12], (const float*)d_in[18]};
    const float* ad_[2] = {(const float*)d_in[13], (const float*)d_in[19]};
    const float* bg[2]  = {(const float*)d_in[14], (const float*)d_in[20]};
    const float* gl[2]  = {(const float*)d_in[15], (const float*)d_in[21]};
    const float* bl[2]  = {(const float*)d_in[16], (const float*)d_in[22]};
    float* out = (float*)d_out;

    cudaFuncSetAttribute(k_gemm, cudaFuncAttributeMaxDynamicSharedMemorySize, GEMM_SMEM);

    // d_deg / d_msum / d_mxenc / d_cnt are zero here: zero-init at module load,
    // re-zeroed by trailing k_zero each call (incl. graph replays).
    k_prep<<<6378, 256>>>(ei, x, Wp, bp, Wg[0], Wg[1]);

    for (int L = 0; L < 2; L++) {
        k_gemm<<<GEMM_GRID, 256, GEMM_SMEM>>>(L, as_[L], ad_[L]);
        k_gat<<<(NN + 7) / 8, 256>>>(bg[L], gl[L], bl[L], L == 0 ? 1 : 0);
    }

    k_pool<<<(NN + 31) / 32, 128>>>(n2g);
    k_head<<<G, 128>>>(Wq1, bq1, gq, beq, Wq2, bq2, out);
    k_zero<<<(NN + 255) / 256, 256>>>();
}

// round 12
// speedup vs baseline: 1.1408x; 1.1408x over previous
#include <cuda_runtime.h>
#include <cuda_bf16.h>
#include <cuda_fp16.h>
#include <math.h>

#define NN    100000
#define EE    1600000
#define H     128
#define HEADS 4
#define DOUT  32
#define G     64
#define FOUT  256
#define NEG_SLOPE 0.2f
#define PAD   64        // padded CSR stride == smem cache capacity (max in-degree ~40)
#define GT    782       // ceil(NN/128) GEMM tiles

// GEMM smem: [sA 128x136 bf16][sW 128x136 bf16]  (stride 136 elems = 272B -> conflict-free ldmatrix)
#define GSTRIDE 136
#define GA_BYTES (128 * GSTRIDE * 2)     // 34816
#define GEMM_SMEM (2 * GA_BYTES)         // 69632

// ---------------- scratch (device globals; no allocation allowed) ----------------
__device__ float         d_h[NN * H];       // current node features (fp32)
__device__ __nv_bfloat16 d_hb[NN * H];      // bf16 mirror of d_h (GEMM A input)
__device__ __half        d_hph[NN * H];     // h @ W in fp16 (gather source)
__device__ __nv_bfloat16 d_Wb[2][H * H];    // bf16 weights (pre-converted)
__device__ float         d_als[NN * HEADS];
__device__ float         d_ald[NN * HEADS];
__device__ int           d_deg[NN];
__device__ int           d_csr_src[(size_t)NN * PAD];
__device__ float         d_msum[G * H];
__device__ unsigned      d_mxenc[G * H];
__device__ float         d_cnt[G];

// ---------------- helpers ----------------
__device__ __forceinline__ unsigned fenc(float f) {
    unsigned u = __float_as_uint(f);
    return (u & 0x80000000u) ? ~u : (u | 0x80000000u);
}
__device__ __forceinline__ float fdec(unsigned e) {
    return (e & 0x80000000u) ? __uint_as_float(e & 0x7fffffffu)
                             : __uint_as_float(~e);
}
__device__ __forceinline__ float gelu_exact(float v) {
    return 0.5f * v * (1.0f + erff(v * 0.70710678118654752f));
}
__device__ __forceinline__ float lrelu(float v) {
    return v > 0.f ? v : NEG_SLOPE * v;
}
__device__ __forceinline__ void cp16(void* s, const void* g, bool valid) {
    unsigned sa = (unsigned)__cvta_generic_to_shared(s);
    int sz = valid ? 16 : 0;
    asm volatile("cp.async.cg.shared.global [%0], [%1], 16, %2;\n"
                 :: "r"(sa), "l"(g), "r"(sz));
}

// ---------------- trailing zero (restores invariant for next call) ----------------
__global__ void k_zero() {
    int t = blockIdx.x * blockDim.x + threadIdx.x;
    if (t < NN) d_deg[t] = 0;
    if (t < G * H) { d_msum[t] = 0.f; d_mxenc[t] = 0u; }
    if (t < G) d_cnt[t] = 0.f;
}

// ---------------- merged setup: CSR fill | input proj | W conversion ----------------
__global__ void k_prep(const int* __restrict__ ei, const float* __restrict__ x,
                       const float* __restrict__ Wp, const float* __restrict__ bp,
                       const float* __restrict__ Wg0, const float* __restrict__ Wg1) {
    __shared__ float sW[16 * 128];
    __shared__ float sx[32][16];
    int b = blockIdx.x;
    int tid = threadIdx.x;          // 256
    if (b < 3125) {
        int e0 = (b * 256 + tid) * 2;
        if (e0 >= EE) return;
        int2 s2 = *(const int2*)(ei + e0);
        int2 dd = *(const int2*)(ei + EE + e0);
        {
            int p = atomicAdd(&d_deg[dd.x], 1);
            if (p < PAD) d_csr_src[(size_t)dd.x * PAD + p] = s2.x;
        }
        {
            int p = atomicAdd(&d_deg[dd.y], 1);
            if (p < PAD) d_csr_src[(size_t)dd.y * PAD + p] = s2.y;
        }
    } else if (b < 6250) {
        int base = (b - 3125) * 32;
        for (int i = tid; i < 16 * 128; i += 256) sW[i] = Wp[i];
        for (int i = tid; i < 32 * 16; i += 256) {
            int r = i >> 4, c = i & 15;
            sx[r][c] = (base + r < NN) ? x[(base + r) * 16 + c] : 0.f;
        }
        __syncthreads();
        int col  = tid & 127;
        int half = tid >> 7;
        float w[16];
#pragma unroll
        for (int k = 0; k < 16; k++) w[k] = sW[k * 128 + col];
        float bb = bp[col];
        for (int n = half * 16; n < half * 16 + 16; n++) {
            int row = base + n;
            if (row >= NN) break;
            float acc = bb;
#pragma unroll
            for (int k = 0; k < 16; k++) acc = fmaf(sx[n][k], w[k], acc);
            float v = gelu_exact(acc);
            d_h[row * H + col]  = v;
            d_hb[row * H + col] = __float2bfloat16(v);
        }
    } else {
        int bb = b - 6250;              // 0..127
        int layer = bb >> 6;
        int off = (bb & 63) * 256 + tid;
        const float* Wsrc = layer ? Wg1 : Wg0;
        d_Wb[layer][off] = __float2bfloat16(Wsrc[off]);
    }
}

// ---------------- raw-MMA GEMM, register epilogue (no C smem round-trip) --------
// 128 threads = 4 warps in 2x2; warp tile 64 rows x 64 cols.
// mma.m16n8k16 bf16: A via ldmatrix.x4, B via ldmatrix.x4.trans from row-major W.
__global__ __launch_bounds__(128, 2) void k_gemm(int layer,
                                                 const float* __restrict__ a_s,
                                                 const float* __restrict__ a_d) {
    extern __shared__ char smem[];
    __nv_bfloat16* sA = (__nv_bfloat16*)smem;               // [128][GSTRIDE]
    __nv_bfloat16* sW = (__nv_bfloat16*)(smem + GA_BYTES);  // [128][GSTRIDE]
    int tid  = threadIdx.x;
    int warp = tid >> 5, lane = tid & 31;
    int rowBase = blockIdx.x * 128;
    const __nv_bfloat16* Wb = d_Wb[layer];

    // load A + W (16 chunks of 16B each per thread per array)
#pragma unroll
    for (int j = 0; j < 16; j++) {
        int idx = j * 128 + tid;        // 0..2047
        int r = idx >> 4, c = idx & 15;
        int grow = rowBase + r;
        cp16(&sA[r * GSTRIDE + c * 8], &d_hb[(size_t)grow * H + c * 8], grow < NN);
        cp16(&sW[r * GSTRIDE + c * 8], &Wb[r * H + c * 8], true);
    }
    asm volatile("cp.async.commit_group;");
    asm volatile("cp.async.wait_group 0;");
    __syncthreads();

    int wr = (warp >> 1) * 64;      // warp row base (in tile)
    int wc = (warp & 1) * 64;       // warp col base

    float d[4][8][4];
#pragma unroll
    for (int M = 0; M < 4; M++)
#pragma unroll
        for (int t = 0; t < 8; t++)
#pragma unroll
            for (int q = 0; q < 4; q++) d[M][t][q] = 0.f;

    int lrow = lane & 7;
    int lsel = (lane >> 3) & 1;
    int lhi  = lane >> 4;

#pragma unroll
    for (int k = 0; k < 8; k++) {
        unsigned a[4][4];
#pragma unroll
        for (int M = 0; M < 4; M++) {
            unsigned addr = (unsigned)__cvta_generic_to_shared(
                &sA[(wr + M * 16 + lrow + lsel * 8) * GSTRIDE + k * 16 + lhi * 8]);
            asm volatile("ldmatrix.sync.aligned.m8n8.x4.shared.b16 {%0,%1,%2,%3}, [%4];"
                         : "=r"(a[M][0]), "=r"(a[M][1]), "=r"(a[M][2]), "=r"(a[M][3])
                         : "r"(addr));
        }
        unsigned b[8][2];
#pragma unroll
        for (int tp = 0; tp < 4; tp++) {
            unsigned addr = (unsigned)__cvta_generic_to_shared(
                &sW[(k * 16 + lrow + lsel * 8) * GSTRIDE + wc + tp * 16 + lhi * 8]);
            asm volatile("ldmatrix.sync.aligned.m8n8.x4.trans.shared.b16 {%0,%1,%2,%3}, [%4];"
                         : "=r"(b[2 * tp][0]), "=r"(b[2 * tp][1]),
                           "=r"(b[2 * tp + 1][0]), "=r"(b[2 * tp + 1][1])
                         : "r"(addr));
        }
#pragma unroll
        for (int M = 0; M < 4; M++)
#pragma unroll
            for (int t = 0; t < 8; t++) {
                asm volatile(
                    "mma.sync.aligned.m16n8k16.row.col.f32.bf16.bf16.f32 "
                    "{%0,%1,%2,%3}, {%4,%5,%6,%7}, {%8,%9}, {%0,%1,%2,%3};"
                    : "+f"(d[M][t][0]), "+f"(d[M][t][1]), "+f"(d[M][t][2]), "+f"(d[M][t][3])
                    : "r"(a[M][0]), "r"(a[M][1]), "r"(a[M][2]), "r"(a[M][3]),
                      "r"(b[t][0]), "r"(b[t][1]));
            }
    }

    // register epilogue: lane l holds rows (g, g+8), cols 2*(l%4)+{0,1} per n-tile
    int g4 = lane >> 2, tg = lane & 3;
    int h0 = wc >> 5;                       // first head of this warp's col range
#pragma unroll
    for (int M = 0; M < 4; M++) {
        int r1 = rowBase + wr + M * 16 + g4;
        int r2 = r1 + 8;
        bool v1 = r1 < NN, v2 = r2 < NN;
        float ps1[2] = {0.f, 0.f}, pd1[2] = {0.f, 0.f};
        float ps2[2] = {0.f, 0.f}, pd2[2] = {0.f, 0.f};
#pragma unroll
        for (int t = 0; t < 8; t++) {
            int c0 = wc + t * 8 + tg * 2;
            float as0 = __ldg(a_s + c0), as1 = __ldg(a_s + c0 + 1);
            float ad0 = __ldg(a_d + c0), ad1 = __ldg(a_d + c0 + 1);
            int ht = t >> 2;
            float v0 = d[M][t][0], v1f = d[M][t][1], v2f = d[M][t][2], v3 = d[M][t][3];
            ps1[ht] += v0 * as0 + v1f * as1;
            pd1[ht] += v0 * ad0 + v1f * ad1;
            ps2[ht] += v2f * as0 + v3 * as1;
            pd2[ht] += v2f * ad0 + v3 * ad1;
            if (v1) *(__half2*)(d_hph + (size_t)r1 * H + c0) = __floats2half2_rn(v0, v1f);
            if (v2) *(__half2*)(d_hph + (size_t)r2 * H + c0) = __floats2half2_rn(v2f, v3);
        }
        // reduce over the 4 lanes of the quad (tg)
#pragma unroll
        for (int o = 1; o <= 2; o <<= 1) {
            ps1[0] += __shfl_xor_sync(0xffffffffu, ps1[0], o);
            ps1[1] += __shfl_xor_sync(0xffffffffu, ps1[1], o);
            pd1[0] += __shfl_xor_sync(0xffffffffu, pd1[0], o);
            pd1[1] += __shfl_xor_sync(0xffffffffu, pd1[1], o);
            ps2[0] += __shfl_xor_sync(0xffffffffu, ps2[0], o);
            ps2[1] += __shfl_xor_sync(0xffffffffu, ps2[1], o);
            pd2[0] += __shfl_xor_sync(0xffffffffu, pd2[0], o);
            pd2[1] += __shfl_xor_sync(0xffffffffu, pd2[1], o);
        }
        if (tg == 0) {
            if (v1) {
                *(float2*)(d_als + r1 * 4 + h0) = make_float2(ps1[0], ps1[1]);
                *(float2*)(d_ald + r1 * 4 + h0) = make_float2(pd1[0], pd1[1]);
            }
            if (v2) {
                *(float2*)(d_als + r2 * 4 + h0) = make_float2(ps2[0], ps2[1]);
                *(float2*)(d_ald + r2 * 4 + h0) = make_float2(pd2[0], pd2[1]);
            }
        }
    }
}

// ---------------- fused GAT layer: 2 nodes per warp (16-lane groups) ------------
__global__ __launch_bounds__(256) void k_gat(const float* __restrict__ bg,
                                             const float* __restrict__ g,
                                             const float* __restrict__ be,
                                             int writeBf) {
    __shared__ int   s_src[16][PAD];
    __shared__ float s_e[16][PAD * 4];
    int hw = threadIdx.x >> 4;          // half-warp group 0..15
    int c  = threadIdx.x & 15;          // lane within group
    int n  = blockIdx.x * 16 + hw;
    bool active = n < NN;
    int deg = 0;
    size_t off0 = 0;
    float4 aldn = make_float4(0.f, 0.f, 0.f, 0.f);
    float4 es   = make_float4(0.f, 0.f, 0.f, 0.f);
    if (active) {
        off0 = (size_t)n * PAD;
        deg = d_deg[n];
        deg = deg < PAD ? deg : PAD;
        aldn = ((const float4*)d_ald)[n];
        float4 asel = ((const float4*)d_als)[n];
        es.x = __expf(lrelu(asel.x + aldn.x));
        es.y = __expf(lrelu(asel.y + aldn.y));
        es.z = __expf(lrelu(asel.z + aldn.z));
        es.w = __expf(lrelu(asel.w + aldn.w));
    }

    // phase A: gather + exp + denom (16-lane strided)
    float4 sum = make_float4(0.f, 0.f, 0.f, 0.f);
    for (int i = c; i < deg; i += 16) {
        int s = __ldg(&d_csr_src[off0 + i]);
        float4 a = __ldg(((const float4*)d_als) + s);
        float ex = __expf(lrelu(a.x + aldn.x));
        float ey = __expf(lrelu(a.y + aldn.y));
        float ez = __expf(lrelu(a.z + aldn.z));
        float ew = __expf(lrelu(a.w + aldn.w));
        s_src[hw][i] = s;
        s_e[hw][i * 4 + 0] = ex; s_e[hw][i * 4 + 1] = ey;
        s_e[hw][i * 4 + 2] = ez; s_e[hw][i * 4 + 3] = ew;
        sum.x += ex; sum.y += ey; sum.z += ez; sum.w += ew;
    }
    __syncwarp();
#pragma unroll
    for (int o = 8; o; o >>= 1) {
        sum.x += __shfl_xor_sync(0xffffffffu, sum.x, o, 16);
        sum.y += __shfl_xor_sync(0xffffffffu, sum.y, o, 16);
        sum.z += __shfl_xor_sync(0xffffffffu, sum.z, o, 16);
        sum.w += __shfl_xor_sync(0xffffffffu, sum.w, o, 16);
    }
    float4 rden;
    rden.x = 1.f / (sum.x + es.x + 1e-16f);
    rden.y = 1.f / (sum.y + es.y + 1e-16f);
    rden.z = 1.f / (sum.z + es.z + 1e-16f);
    rden.w = 1.f / (sum.w + es.w + 1e-16f);

    // phase C: lane c owns cols c*8..c*8+7 (one head per 4 lanes)
    int head = c >> 2;
    float rd  = head == 0 ? rden.x : head == 1 ? rden.y : head == 2 ? rden.z : rden.w;
    float esh = head == 0 ? es.x   : head == 1 ? es.y   : head == 2 ? es.z   : es.w;
    float4 lo = make_float4(0.f,0.f,0.f,0.f), hi = lo;
    if (active) {
        lo = *(const float4*)(d_h + (size_t)n * H + c * 8);
        hi = *(const float4*)(d_h + (size_t)n * H + c * 8 + 4);
        float4 b0 = __ldg((const float4*)(bg + c * 8));
        float4 b1 = __ldg((const float4*)(bg + c * 8 + 4));
        lo.x += b0.x; lo.y += b0.y; lo.z += b0.z; lo.w += b0.w;
        hi.x += b1.x; hi.y += b1.y; hi.z += b1.z; hi.w += b1.w;
        // self message
        float a0 = esh * rd;
        uint4 u = __ldg((const uint4*)(d_hph + (size_t)n * H + c * 8));
        float2 p0 = __half22float2(*(__half2*)&u.x);
        float2 p1 = __half22float2(*(__half2*)&u.y);
        float2 p2 = __half22float2(*(__half2*)&u.z);
        float2 p3 = __half22float2(*(__half2*)&u.w);
        lo.x = fmaf(p0.x, a0, lo.x); lo.y = fmaf(p0.y, a0, lo.y);
        lo.z = fmaf(p1.x, a0, lo.z); lo.w = fmaf(p1.y, a0, lo.w);
        hi.x = fmaf(p2.x, a0, hi.x); hi.y = fmaf(p2.y, a0, hi.y);
        hi.z = fmaf(p3.x, a0, hi.z); hi.w = fmaf(p3.y, a0, hi.w);
    }
    int i = 0;
    for (; i + 4 <= deg; i += 4) {
        int   sv[4]; float av[4]; uint4 uv[4];
#pragma unroll
        for (int j = 0; j < 4; j++) {
            sv[j] = s_src[hw][i + j];
            av[j] = s_e[hw][(i + j) * 4 + head] * rd;
        }
#pragma unroll
        for (int j = 0; j < 4; j++)
            uv[j] = __ldg((const uint4*)(d_hph + (size_t)sv[j] * H + c * 8));
#pragma unroll
        for (int j = 0; j < 4; j++) {
            float2 p0 = __half22float2(*(__half2*)&uv[j].x);
            float2 p1 = __half22float2(*(__half2*)&uv[j].y);
            float2 p2 = __half22float2(*(__half2*)&uv[j].z);
            float2 p3 = __half22float2(*(__half2*)&uv[j].w);
            lo.x = fmaf(p0.x, av[j], lo.x); lo.y = fmaf(p0.y, av[j], lo.y);
            lo.z = fmaf(p1.x, av[j], lo.z); lo.w = fmaf(p1.y, av[j], lo.w);
            hi.x = fmaf(p2.x, av[j], hi.x); hi.y = fmaf(p2.y, av[j], hi.y);
            hi.z = fmaf(p3.x, av[j], hi.z); hi.w = fmaf(p3.y, av[j], hi.w);
        }
    }
    for (; i < deg; i++) {
        int s = s_src[hw][i];
        float a0 = s_e[hw][i * 4 + head] * rd;
        uint4 u = __ldg((const uint4*)(d_hph + (size_t)s * H + c * 8));
        float2 p0 = __half22float2(*(__half2*)&u.x);
        float2 p1 = __half22float2(*(__half2*)&u.y);
        float2 p2 = __half22float2(*(__half2*)&u.z);
        float2 p3 = __half22float2(*(__half2*)&u.w);
        lo.x = fmaf(p0.x, a0, lo.x); lo.y = fmaf(p0.y, a0, lo.y);
        lo.z = fmaf(p1.x, a0, lo.z); lo.w = fmaf(p1.y, a0, lo.w);
        hi.x = fmaf(p2.x, a0, hi.x); hi.y = fmaf(p2.y, a0, hi.y);
        hi.z = fmaf(p3.x, a0, hi.z); hi.w = fmaf(p3.y, a0, hi.w);
    }

    // fused layernorm -> d_h (+ bf16 mirror for next GEMM)
    __syncwarp();
    float sm = lo.x + lo.y + lo.z + lo.w + hi.x + hi.y + hi.z + hi.w;
#pragma unroll
    for (int o = 8; o; o >>= 1) sm += __shfl_xor_sync(0xffffffffu, sm, o, 16);
    float mu = sm * (1.f / 128.f);
    float d0 = lo.x - mu, d1 = lo.y - mu, d2 = lo.z - mu, d3 = lo.w - mu;
    float d4 = hi.x - mu, d5 = hi.y - mu, d6 = hi.z - mu, d7 = hi.w - mu;
    float q = d0*d0 + d1*d1 + d2*d2 + d3*d3 + d4*d4 + d5*d5 + d6*d6 + d7*d7;
#pragma unroll
    for (int o = 8; o; o >>= 1) q += __shfl_xor_sync(0xffffffffu, q, o, 16);
    float rstd = rsqrtf(q * (1.f / 128.f) + 1e-5f);
    if (active) {
        float4 g0 = __ldg((const float4*)(g + c * 8));
        float4 g1 = __ldg((const float4*)(g + c * 8 + 4));
        float4 e0 = __ldg((const float4*)(be + c * 8));
        float4 e1 = __ldg((const float4*)(be + c * 8 + 4));
        float4 o0, o1;
        o0.x = d0 * rstd * g0.x + e0.x;
        o0.y = d1 * rstd * g0.y + e0.y;
        o0.z = d2 * rstd * g0.z + e0.z;
        o0.w = d3 * rstd * g0.w + e0.w;
        o1.x = d4 * rstd * g1.x + e1.x;
        o1.y = d5 * rstd * g1.y + e1.y;
        o1.z = d6 * rstd * g1.z + e1.z;
        o1.w = d7 * rstd * g1.w + e1.w;
        *(float4*)(d_h + (size_t)n * H + c * 8)     = o0;
        *(float4*)(d_h + (size_t)n * H + c * 8 + 4) = o1;
        if (writeBf) {
            __nv_bfloat162 b01 = __floats2bfloat162_rn(o0.x, o0.y);
            __nv_bfloat162 b23 = __floats2bfloat162_rn(o0.z, o0.w);
            __nv_bfloat162 b45 = __floats2bfloat162_rn(o1.x, o1.y);
            __nv_bfloat162 b67 = __floats2bfloat162_rn(o1.z, o1.w);
            uint4 ub = make_uint4(*(unsigned*)&b01, *(unsigned*)&b23,
                                  *(unsigned*)&b45, *(unsigned*)&b67);
            *(uint4*)(d_hb + (size_t)n * H + c * 8) = ub;
        }
    }
}

// ---------------- pooling ----------------
__global__ void k_pool(const int* __restrict__ n2g) {
    __shared__ int sg[32];
    int base = blockIdx.x * 32;
    int c = threadIdx.x; // 128
    if (c < 32) sg[c] = (base + c < NN) ? n2g[base + c] : -1;
    __syncthreads();
    float sum = 0.f, mx = -3.4e38f;
    int gcur = sg[0];
    int cl = 0;
    for (int i = 0; i < 32; i++) {
        int node = base + i;
        if (node >= NN) break;
        int gg = sg[i];
        if (gg != gcur) {
            atomicAdd(&d_msum[gcur * H + c], sum);
            atomicMax(&d_mxenc[gcur * H + c], fenc(mx));
            if (c == 0) atomicAdd(&d_cnt[gcur], (float)cl);
            sum = 0.f; mx = -3.4e38f; cl = 0; gcur = gg;
        }
        float v = d_h[(size_t)node * H + c];
        sum += v; mx = fmaxf(mx, v); cl++;
    }
    atomicAdd(&d_msum[gcur * H + c], sum);
    atomicMax(&d_mxenc[gcur * H + c], fenc(mx));
    if (c == 0) atomicAdd(&d_cnt[gcur], (float)cl);
}

// ---------------- head MLP ----------------
__global__ void k_head(const float* __restrict__ Wq1, const float* __restrict__ bq1,
                       const float* __restrict__ gq, const float* __restrict__ beq,
                       const float* __restrict__ Wq2, const float* __restrict__ bq2,
                       float* __restrict__ out) {
    __shared__ float semb[256];
    __shared__ float sp[128];
    __shared__ float sred[8];
    int g = blockIdx.x;
    int t = threadIdx.x; // 128
    float c = fmaxf(d_cnt[g], 1.f);
    semb[t]       = d_msum[g * H + t] / c;
    semb[128 + t] = fdec(d_mxenc[g * H + t]);
    __syncthreads();
    float p = bq1[t];
    for (int k = 0; k < 256; k++) p = fmaf(semb[k], Wq1[k * 128 + t], p);
    float s = p;
#pragma unroll
    for (int o = 16; o; o >>= 1) s += __shfl_xor_sync(0xffffffffu, s, o);
    if ((t & 31) == 0) sred[t >> 5] = s;
    __syncthreads();
    float mu = (sred[0] + sred[1] + sred[2] + sred[3]) * (1.f / 128.f);
    float dx = p - mu;
    float q = dx * dx;
#pragma unroll
    for (int o = 16; o; o >>= 1) q += __shfl_xor_sync(0xffffffffu, q, o);
    if ((t & 31) == 0) sred[4 + (t >> 5)] = q;
    __syncthreads();
    float var = (sred[4] + sred[5] + sred[6] + sred[7]) * (1.f / 128.f);
    float v = dx * rsqrtf(var + 1e-5f) * gq[t] + beq[t];
    sp[t] = gelu_exact(v);
    __syncthreads();
#pragma unroll
    for (int half = 0; half < 2; half++) {
        int o = t + half * 128;
        float acc = bq2[o];
        for (int k = 0; k < 128; k++) acc = fmaf(sp[k], Wq2[k * 256 + o], acc);
        out[g * 256 + o] = acc;
    }
}

// ---------------- launch ----------------
extern "C" void kernel_launch(void* const* d_in, const int* in_sizes, int n_in,
                              void* d_out, int out_size) {
    const float* x   = (const float*)d_in[0];
    const int*   ei  = (const int*)  d_in[1];
    const int*   n2g = (const int*)  d_in[2];
    const float* Wp  = (const float*)d_in[3];
    const float* bp  = (const float*)d_in[4];
    const float* Wq1 = (const float*)d_in[5];
    const float* bq1 = (const float*)d_in[6];
    const float* gq  = (const float*)d_in[7];
    const float* beq = (const float*)d_in[8];
    const float* Wq2 = (const float*)d_in[9];
    const float* bq2 = (const float*)d_in[10];
    const float* Wg[2]  = {(const float*)d_in[11], (const float*)d_in[17]};
    const float* as_[2] = {(const float*)d_in[12], (const float*)d_in[18]};
    const float* ad_[2] = {(const float*)d_in[13], (const float*)d_in[19]};
    const float* bg[2]  = {(const float*)d_in[14], (const float*)d_in[20]};
    const float* gl[2]  = {(const float*)d_in[15], (const float*)d_in[21]};
    const float* bl[2]  = {(const float*)d_in[16], (const float*)d_in[22]};
    float* out = (float*)d_out;

    cudaFuncSetAttribute(k_gemm, cudaFuncAttributeMaxDynamicSharedMemorySize, GEMM_SMEM);

    // d_deg / d_msum / d_mxenc / d_cnt are zero here: zero-init at module load,
    // re-zeroed by trailing k_zero each call (incl. graph replays).
    k_prep<<<6378, 256>>>(ei, x, Wp, bp, Wg[0], Wg[1]);

    for (int L = 0; L < 2; L++) {
        k_gemm<<<GT, 128, GEMM_SMEM>>>(L, as_[L], ad_[L]);
        k_gat<<<(NN + 15) / 16, 256>>>(bg[L], gl[L], bl[L], L == 0 ? 1 : 0);
    }

    k_pool<<<(NN + 31) / 32, 128>>>(n2g);
    k_head<<<G, 128>>>(Wq1, bq1, gq, beq, Wq2, bq2, out);
    k_zero<<<(NN + 255) / 256, 256>>>();
}